// round 4
// baseline (speedup 1.0000x reference)
#include <cuda_runtime.h>
#include <stdint.h>

// MaskPyramids, fused single-pass: every output element written once with its
// final value. out[inst, :] = concat over 5 levels of a 28x28 gaussian window
// placed at round(pos/200*H) within each HxH level grid.
//
// Rounding replicates XLA's div->mul-by-reciprocal rewrite (verified R3):
//   lh = rint( fl( fl(p * fl(1/200)) * H ) )   all f32 RN-even.

#define N_INST   512
#define G        28
#define CTRK     13
#define PER_INST 53294   // 40000 + 10000 + 2500 + 625 + 169
#define CHUNK    1024    // elements per block (256 thr * 4)
#define NCHUNKS  53      // ceil(53294/1024)

__device__ __forceinline__ float elem_value(int off, float pp0, float pp1,
                                            const float* __restrict__ mask) {
    // level select
    int base, H; unsigned M; float Hf;
    if (off < 40000)      { base = 0;     H = 200; M = 21474837u;  Hf = 200.f; }
    else if (off < 50000) { base = 40000; H = 100; M = 42949673u;  Hf = 100.f; }
    else if (off < 52500) { base = 50000; H = 50;  M = 85899346u;  Hf = 50.f;  }
    else if (off < 53125) { base = 52500; H = 25;  M = 171798692u; Hf = 25.f;  }
    else                  { base = 53125; H = 13;  M = 330382100u; Hf = 13.f;  }

    int loff = off - base;
    int row  = (int)(((unsigned long long)(unsigned)loff * M) >> 32); // exact loff/H
    int col  = loff - row * H;

    // XLA-faithful center: rint(p * fl(1/200) * H), f32 RN-even throughout.
    int lh = (int)rintf(__fmul_rn(pp0, Hf));
    int lw = (int)rintf(__fmul_rn(pp1, Hf));

    int si = row - lh + CTRK;   // = CTR + row - lh
    int sj = col - lw + CTRK;

    float v = 0.0f;
    if ((unsigned)si < (unsigned)G && (unsigned)sj < (unsigned)G)
        v = __ldg(&mask[si * G + sj]);
    return v;
}

__global__ void __launch_bounds__(256) fused_kernel(const int* __restrict__ pos,
                                                    const float* __restrict__ mask,
                                                    float* __restrict__ out) {
    const int inst  = blockIdx.y;
    const int chunk = blockIdx.x;

    const int p0 = __ldg(&pos[2 * inst + 0]);
    const int p1 = __ldg(&pos[2 * inst + 1]);
    const float recip = 0.005f;  // == fl(1/200) bit-exactly
    const float pp0 = __fmul_rn((float)p0, recip);
    const float pp1 = __fmul_rn((float)p1, recip);

    const int off0 = chunk * CHUNK + threadIdx.x * 4;
    float* dst = out + (long long)inst * PER_INST + off0;

    if (off0 + 3 < PER_INST) {
        float v0 = elem_value(off0 + 0, pp0, pp1, mask);
        float v1 = elem_value(off0 + 1, pp0, pp1, mask);
        float v2 = elem_value(off0 + 2, pp0, pp1, mask);
        float v3 = elem_value(off0 + 3, pp0, pp1, mask);
        if ((inst & 1) == 0) {
            // inst*53294 % 4 == 0 -> 16B aligned
            *reinterpret_cast<float4*>(dst) = make_float4(v0, v1, v2, v3);
        } else {
            // 8B aligned only
            reinterpret_cast<float2*>(dst)[0] = make_float2(v0, v1);
            reinterpret_cast<float2*>(dst)[1] = make_float2(v2, v3);
        }
    } else {
        // tail of the row (rare: last chunk only)
        #pragma unroll
        for (int k = 0; k < 4; k++) {
            int off = off0 + k;
            if (off < PER_INST)
                dst[k] = elem_value(off, pp0, pp1, mask);
        }
    }
}

extern "C" void kernel_launch(void* const* d_in, const int* in_sizes, int n_in,
                              void* d_out, int out_size) {
    const int*   pos  = (const int*)d_in[0];      // int32 [512, 2]
    const float* mask = (const float*)d_in[1];    // float32 [28, 28]
    float*       out  = (float*)d_out;            // float32 [512, 53294]

    dim3 grid(NCHUNKS, N_INST);
    fused_kernel<<<grid, 256>>>(pos, mask, out);
}

// round 5
// speedup vs baseline: 1.1859x; 1.1859x over previous
#include <cuda_runtime.h>
#include <stdint.h>

// MaskPyramids single-pass, level-specialized.
// out[inst, :] = concat over 5 levels of a 28x28 gaussian window placed at
// round(pos/200*H) in each HxH grid; everything else zero.
//
// Level 0 (200x200, 75% of bytes) and level 1 (100x100, 19%) get dedicated
// compile-time-H kernels with a zero fast path; levels 2-4 (6%) share a
// generic tail kernel. Rounding replicates XLA's div->reciprocal-mul rewrite
// (verified exact in R3): rint( fl( fl(p * fl(1/200)) * H ) ), f32 RN-even.

#define N_INST   512
#define G        28
#define CTRK     13
#define PER_INST 53294   // 40000 + 10000 + 2500 + 625 + 169

template<int H, int BASE>
__global__ void __launch_bounds__(256)
level_kernel(const int* __restrict__ pos,
             const float* __restrict__ mask,
             float* __restrict__ out) {
    const int inst = blockIdx.y;
    const int off  = (blockIdx.x * 256 + threadIdx.x) * 4;
    if (off >= H * H) return;

    // window center (identical arithmetic to the R3-passing kernel)
    const float recip = 0.005f;  // fl(1/200) bit-exactly
    const int p0 = __ldg(&pos[2 * inst + 0]);
    const int p1 = __ldg(&pos[2 * inst + 1]);
    const int lh = (int)rintf(__fmul_rn(__fmul_rn((float)p0, recip), (float)H));
    const int lw = (int)rintf(__fmul_rn(__fmul_rn((float)p1, recip), (float)H));

    const int row = off / H;          // compile-time const division
    const int col = off - row * H;    // chunk never straddles a row (H%4==0)

    const int si = row - lh + CTRK;           // mask row index
    const int b0 = lw - CTRK;                 // first grid col of window

    float4 v = make_float4(0.f, 0.f, 0.f, 0.f);
    if ((unsigned)si < (unsigned)G && (col + 3 >= b0) && (col <= b0 + G - 1)) {
        const float* mrow = mask + si * G;
        int sj = col - b0;
        if ((unsigned)(sj + 0) < (unsigned)G) v.x = __ldg(&mrow[sj + 0]);
        if ((unsigned)(sj + 1) < (unsigned)G) v.y = __ldg(&mrow[sj + 1]);
        if ((unsigned)(sj + 2) < (unsigned)G) v.z = __ldg(&mrow[sj + 2]);
        if ((unsigned)(sj + 3) < (unsigned)G) v.w = __ldg(&mrow[sj + 3]);
    }

    float* dst = out + inst * PER_INST + BASE + off;
    if ((inst & 1) == 0) {
        *reinterpret_cast<float4*>(dst) = v;           // 16B aligned
    } else {
        reinterpret_cast<float2*>(dst)[0] = make_float2(v.x, v.y);  // 8B aligned
        reinterpret_cast<float2*>(dst)[1] = make_float2(v.z, v.w);
    }
}

// Levels 2-4: offsets [50000, 53294) within each instance row. Scalar.
__global__ void __launch_bounds__(256)
tail_kernel(const int* __restrict__ pos,
            const float* __restrict__ mask,
            float* __restrict__ out) {
    const int inst = blockIdx.y;
    const int idx  = blockIdx.x * 256 + threadIdx.x;   // 0..3293
    if (idx >= 3294) return;

    int H, loff;
    if (idx < 2500)      { H = 50; loff = idx; }
    else if (idx < 3125) { H = 25; loff = idx - 2500; }
    else                 { H = 13; loff = idx - 3125; }

    const float recip = 0.005f;
    const int p0 = __ldg(&pos[2 * inst + 0]);
    const int p1 = __ldg(&pos[2 * inst + 1]);
    const int lh = (int)rintf(__fmul_rn(__fmul_rn((float)p0, recip), (float)H));
    const int lw = (int)rintf(__fmul_rn(__fmul_rn((float)p1, recip), (float)H));

    const int row = loff / H;
    const int col = loff - row * H;
    const int si  = row - lh + CTRK;
    const int sj  = col - lw + CTRK;

    float v = 0.0f;
    if ((unsigned)si < (unsigned)G && (unsigned)sj < (unsigned)G)
        v = __ldg(&mask[si * G + sj]);

    out[inst * PER_INST + 50000 + idx] = v;
}

extern "C" void kernel_launch(void* const* d_in, const int* in_sizes, int n_in,
                              void* d_out, int out_size) {
    const int*   pos  = (const int*)d_in[0];      // int32 [512, 2]
    const float* mask = (const float*)d_in[1];    // float32 [28, 28]
    float*       out  = (float*)d_out;            // float32 [512, 53294]

    level_kernel<200, 0>    <<<dim3(40, N_INST), 256>>>(pos, mask, out);  // 40000 elems
    level_kernel<100, 40000><<<dim3(10, N_INST), 256>>>(pos, mask, out);  // 10000 elems
    tail_kernel             <<<dim3(13, N_INST), 256>>>(pos, mask, out);  // 3294 elems
}

// round 6
// speedup vs baseline: 1.5743x; 1.3276x over previous
#include <cuda_runtime.h>
#include <stdint.h>

// MaskPyramids single-pass, single-launch, level-specialized per block.
// out[inst, :] = concat over 5 levels of a 28x28 gaussian window placed at
// round(pos/200*H) in each HxH grid; everything else zero.
//
// grid = (14, 512): bx 0-9 -> level 200x200, bx 10-12 -> level 100x100,
// bx 13 -> levels 50/25/13 (tail). Each thread handles 4 float4 chunks
// (strided) so pos-load latency + center computation amortize and 4 stores
// stay in flight.
//
// Rounding replicates XLA's div->reciprocal-mul rewrite (verified exact R3):
//   rint( fl( fl(p * fl(1/200)) * H ) ), all f32 RN-even.

#define N_INST   512
#define G        28
#define CTRK     13
#define PER_INST 53294   // 40000 + 10000 + 2500 + 625 + 169

__device__ __forceinline__ void store4(float* dst, float4 v, bool aligned16) {
    if (aligned16) {
        *reinterpret_cast<float4*>(dst) = v;
    } else {
        reinterpret_cast<float2*>(dst)[0] = make_float2(v.x, v.y);
        reinterpret_cast<float2*>(dst)[1] = make_float2(v.z, v.w);
    }
}

template<int H, int BASE>
__device__ __forceinline__ void do_level(int chunk, float pp0, float pp1,
                                         const float* __restrict__ mask,
                                         float* __restrict__ outrow,
                                         bool aligned16) {
    const int lh = (int)rintf(__fmul_rn(pp0, (float)H));
    const int lw = (int)rintf(__fmul_rn(pp1, (float)H));
    const int c0 = CTRK - lh;         // si = row + c0
    const int b0 = lw - CTRK;         // sj = col - b0

    const int f4base = chunk * 1024 + threadIdx.x;   // float4 index
    #pragma unroll
    for (int k = 0; k < 4; k++) {
        const int off = (f4base + k * 256) * 4;
        if (off < H * H) {
            const int row = off / H;            // compile-time magic div
            const int col = off - row * H;      // H%4==0: no row straddle
            const int si  = row + c0;
            const int sj  = col - b0;
            float4 v = make_float4(0.f, 0.f, 0.f, 0.f);
            if ((unsigned)si < (unsigned)G && sj > -4 && sj < G) {
                const float* mrow = mask + si * G;
                if ((unsigned)(sj + 0) < (unsigned)G) v.x = __ldg(&mrow[sj + 0]);
                if ((unsigned)(sj + 1) < (unsigned)G) v.y = __ldg(&mrow[sj + 1]);
                if ((unsigned)(sj + 2) < (unsigned)G) v.z = __ldg(&mrow[sj + 2]);
                if ((unsigned)(sj + 3) < (unsigned)G) v.w = __ldg(&mrow[sj + 3]);
            }
            store4(outrow + BASE + off, v, aligned16);
        }
    }
}

template<int H, int BASE, int N>
__device__ __forceinline__ void do_tail_level(float pp0, float pp1,
                                              const float* __restrict__ mask,
                                              float* __restrict__ outrow) {
    const int lh = (int)rintf(__fmul_rn(pp0, (float)H));
    const int lw = (int)rintf(__fmul_rn(pp1, (float)H));
    const int c0 = CTRK - lh;
    const int b0 = lw - CTRK;
    for (int idx = threadIdx.x; idx < N; idx += 256) {
        const int row = idx / H;                // compile-time magic div
        const int col = idx - row * H;
        const int si  = row + c0;
        const int sj  = col - b0;
        float v = 0.0f;
        if ((unsigned)si < (unsigned)G && (unsigned)sj < (unsigned)G)
            v = __ldg(&mask[si * G + sj]);
        outrow[BASE + idx] = v;
    }
}

__global__ void __launch_bounds__(256)
fused_kernel(const int* __restrict__ pos,
             const float* __restrict__ mask,
             float* __restrict__ out) {
    const int inst = blockIdx.y;
    const int bx   = blockIdx.x;

    const float recip = 0.005f;  // fl(1/200) bit-exactly
    const float pp0 = __fmul_rn((float)__ldg(&pos[2 * inst + 0]), recip);
    const float pp1 = __fmul_rn((float)__ldg(&pos[2 * inst + 1]), recip);

    float* outrow = out + inst * PER_INST;
    const bool aligned16 = ((inst & 1) == 0);   // row stride 53294 % 4 == 2

    if (bx < 10) {
        do_level<200, 0>(bx, pp0, pp1, mask, outrow, aligned16);
    } else if (bx < 13) {
        do_level<100, 40000>(bx - 10, pp0, pp1, mask, outrow, aligned16);
    } else {
        do_tail_level<50, 50000, 2500>(pp0, pp1, mask, outrow);
        do_tail_level<25, 52500, 625>(pp0, pp1, mask, outrow);
        do_tail_level<13, 53125, 169>(pp0, pp1, mask, outrow);
    }
}

extern "C" void kernel_launch(void* const* d_in, const int* in_sizes, int n_in,
                              void* d_out, int out_size) {
    const int*   pos  = (const int*)d_in[0];      // int32 [512, 2]
    const float* mask = (const float*)d_in[1];    // float32 [28, 28]
    float*       out  = (float*)d_out;            // float32 [512, 53294]

    fused_kernel<<<dim3(14, N_INST), 256>>>(pos, mask, out);
}